// round 10
// baseline (speedup 1.0000x reference)
#include <cuda_runtime.h>
#include <cstdint>

#define BATCH   256
#define DIN     5120
#define RNK     160
#define NST     16
#define NOUT    192   // 160 (dt_low) + 16 (Bp) + 16 (C)
#define KSPLIT  64

// Scratch
__device__ float g_Part[KSPLIT * BATCH * NOUT]; // split-K partials [ks][b][j]
__device__ float g_Pt[NOUT * BATCH];            // P^T [out][batch]
__device__ float g_dt[BATCH * DIN];             // softplus'd delta [b][d]
__device__ float g_As2[DIN * NST];              // -exp(A_log)*log2e
__device__ float g_Ct[BATCH * NST];             // C transposed [b][n]
__device__ float g_SBC[BATCH];                  // sum_n Bp*C per batch

// ---------- f32x2 helpers ----------
__device__ __forceinline__ unsigned long long pack2(float lo, float hi) {
    unsigned long long r;
    asm("mov.b64 %0, {%1, %2};" : "=l"(r)
        : "r"(__float_as_uint(lo)), "r"(__float_as_uint(hi)));
    return r;
}
__device__ __forceinline__ void unpack2(unsigned long long v, float& lo, float& hi) {
    unsigned int a, b;
    asm("mov.b64 {%0, %1}, %2;" : "=r"(a), "=r"(b) : "l"(v));
    lo = __uint_as_float(a);
    hi = __uint_as_float(b);
}
__device__ __forceinline__ void ffma2(unsigned long long& d,
                                      unsigned long long a,
                                      unsigned long long b) {
    asm("fma.rn.f32x2 %0, %1, %2, %0;" : "+l"(d) : "l"(a), "l"(b));
}
__device__ __forceinline__ float ex2f(float x) {
    float r;
    asm("ex2.approx.ftz.f32 %0, %1;" : "=f"(r) : "f"(x));
    return r;
}
__device__ __forceinline__ float softplus20(float z) {
    return (z > 20.0f) ? z : fmaxf(z, 0.0f) + log1pf(__expf(-fabsf(z)));
}

// ---------- K1: split-K proj GEMM, W direct from gmem, no smem W ----------
// grid (64 ksplits of 80, 8 btiles of 32), block 256 = 8 warps, >=3 CTAs/SM.
// Warp w handles 24 outputs [24w,24w+24) via 6 uniform LDG.128 per k;
// lane handles batch b0+lane. Partials to g_Part[ks][b][j] (no atomics).
#define K1_KC 80
#define K1_BT 32
#define K1_SMEM (K1_KC * 33 * 4)     // Xst only, 10.5 KB

__global__ __launch_bounds__(256, 3)
void k1_proj(const float* __restrict__ x,
             const float* __restrict__ Wd,
             const float* __restrict__ WB,
             const float* __restrict__ WC,
             const float* __restrict__ Alog) {
    extern __shared__ float sm[];
    float* Xst = sm;                   // [k][b] 80 x 33

    const int t   = threadIdx.x;
    const int ks  = blockIdx.x;
    const int k0  = ks * K1_KC;
    const int b0  = blockIdx.y * K1_BT;
    const int cta = blockIdx.y * gridDim.x + blockIdx.x;   // 0..511

    // As2 precompute: first 256 CTAs x 320 elems (80 float4)
    if (cta < 256 && t < 80) {
        int idx = cta * 320 + t * 4;
        float4 a = *(const float4*)&Alog[idx];
        const float c = -1.44269504088896f;
        float4 r;
        r.x = c * __expf(a.x); r.y = c * __expf(a.y);
        r.z = c * __expf(a.z); r.w = c * __expf(a.w);
        *(float4*)&g_As2[idx] = r;
    }

    // load X transposed: 32 rows x 20 quads = 640 float4
    for (int e = t; e < K1_BT * (K1_KC / 4); e += 256) {
        int row = e / 20;
        int q   = e - row * 20;
        float4 v = *(const float4*)&x[(b0 + row) * DIN + k0 + q * 4];
        int base = (q * 4) * 33 + row;
        Xst[base]      = v.x;
        Xst[base + 33] = v.y;
        Xst[base + 66] = v.z;
        Xst[base + 99] = v.w;
    }
    __syncthreads();

    const int w    = t >> 5;
    const int lane = t & 31;
    const int jb   = w * 24;

    // per-quad uniform W pointers + strides
    const float* wptr[6];
    int wstr[6];
#pragma unroll
    for (int qd = 0; qd < 6; qd++) {
        int j = jb + qd * 4;
        if (j < RNK)      { wptr[qd] = Wd + (size_t)k0 * RNK + j;         wstr[qd] = RNK; }
        else if (j < 176) { wptr[qd] = WB + (size_t)k0 * NST + (j - 160); wstr[qd] = NST; }
        else              { wptr[qd] = WC + (size_t)k0 * NST + (j - 176); wstr[qd] = NST; }
    }

    unsigned long long acc[12];
#pragma unroll
    for (int j = 0; j < 12; j++) acc[j] = 0ull;

    // distance-1 double buffer of W rows in registers
    ulonglong2 WA[6];
#pragma unroll
    for (int qd = 0; qd < 6; qd++) {
        WA[qd] = *(const ulonglong2*)wptr[qd];
        wptr[qd] += wstr[qd];
    }
    const float* xp = &Xst[lane];
    float xA = xp[0];

#pragma unroll 1
    for (int k = 0; k < K1_KC - 1; k++) {
        ulonglong2 WN[6];
#pragma unroll
        for (int qd = 0; qd < 6; qd++) {
            WN[qd] = *(const ulonglong2*)wptr[qd];
            wptr[qd] += wstr[qd];
        }
        float xN = xp[(k + 1) * 33];

        unsigned long long x2 = pack2(xA, xA);
#pragma unroll
        for (int qd = 0; qd < 6; qd++) {
            ffma2(acc[2 * qd],     x2, WA[qd].x);
            ffma2(acc[2 * qd + 1], x2, WA[qd].y);
        }
#pragma unroll
        for (int qd = 0; qd < 6; qd++) WA[qd] = WN[qd];
        xA = xN;
    }
    {   // peeled last row
        unsigned long long x2 = pack2(xA, xA);
#pragma unroll
        for (int qd = 0; qd < 6; qd++) {
            ffma2(acc[2 * qd],     x2, WA[qd].x);
            ffma2(acc[2 * qd + 1], x2, WA[qd].y);
        }
    }

    // epilogue: plain stores of partials, [ks][b][j] layout
    {
        float v[24];
#pragma unroll
        for (int j = 0; j < 12; j++) unpack2(acc[j], v[2 * j], v[2 * j + 1]);
        size_t base = ((size_t)ks * BATCH + b0 + lane) * NOUT + jb;
#pragma unroll
        for (int p = 0; p < 6; p++)
            *(float4*)&g_Part[base + p * 4] = *(float4*)&v[p * 4];
    }
}

// ---------- K1R: reduce split-K partials -> g_Pt[j][b] ----------
__global__ __launch_bounds__(256)
void k1r_reduce() {
    int t  = blockIdx.x * 256 + threadIdx.x;   // 0..12287
    int b  = t / 48;
    int jq = t - b * 48;
    int j  = jq * 4;

    float4 s0 = {0,0,0,0}, s1 = {0,0,0,0}, s2 = {0,0,0,0}, s3 = {0,0,0,0};
    size_t base = (size_t)b * NOUT + j;
    const size_t stride = (size_t)BATCH * NOUT;
#pragma unroll 4
    for (int ks = 0; ks < KSPLIT; ks += 4) {
        float4 a0 = *(const float4*)&g_Part[base + (ks + 0) * stride];
        float4 a1 = *(const float4*)&g_Part[base + (ks + 1) * stride];
        float4 a2 = *(const float4*)&g_Part[base + (ks + 2) * stride];
        float4 a3 = *(const float4*)&g_Part[base + (ks + 3) * stride];
        s0.x += a0.x; s0.y += a0.y; s0.z += a0.z; s0.w += a0.w;
        s1.x += a1.x; s1.y += a1.y; s1.z += a1.z; s1.w += a1.w;
        s2.x += a2.x; s2.y += a2.y; s2.z += a2.z; s2.w += a2.w;
        s3.x += a3.x; s3.y += a3.y; s3.z += a3.z; s3.w += a3.w;
    }
    g_Pt[(j + 0) * BATCH + b] = (s0.x + s1.x) + (s2.x + s3.x);
    g_Pt[(j + 1) * BATCH + b] = (s0.y + s1.y) + (s2.y + s3.y);
    g_Pt[(j + 2) * BATCH + b] = (s0.z + s1.z) + (s2.z + s3.z);
    g_Pt[(j + 3) * BATCH + b] = (s0.w + s1.w) + (s2.w + s3.w);
}

// ---------- K2: dt = softplus(P_low @ W_dt + b_dt); also Ct + SBC ----------
// grid (40 d-blocks of 128, 8 btiles of 32), block 256, 3 CTAs/SM.
#define K2B 32
#define K2_SMEM (((RNK + 1) * 64 + (RNK + 1) * K2B) * 4)

__global__ __launch_bounds__(256, 3)
void k2_dt(const float* __restrict__ Wdt,
           const float* __restrict__ bdt) {
    extern __shared__ float sm[];
    float* Wds = sm;                      // [r][dj] (160+1) x 64
    float* Ps  = sm + (RNK + 1) * 64;     // [r][bi] (160+1) x 32

    const int t  = threadIdx.x;
    const int b0 = blockIdx.y * K2B;
    const int tx = t & 15;   // dj group of 4
    const int ty = t >> 4;   // bi group of 2

    for (int e = t; e < RNK * 8; e += 256) {
        int r = e >> 3, q = e & 7;
        *(float4*)&Ps[r * K2B + q * 4] = *(const float4*)&g_Pt[r * BATCH + b0 + q * 4];
    }

    for (int chunk = 0; chunk < 2; chunk++) {
        const int d0 = blockIdx.x * 128 + chunk * 64;
        __syncthreads();
        for (int e = t; e < RNK * 16; e += 256) {
            int r = e >> 4, q = e & 15;
            *(float4*)&Wds[r * 64 + q * 4] =
                *(const float4*)&Wdt[r * DIN + d0 + q * 4];
        }
        __syncthreads();

        unsigned long long acc[2][2];
        acc[0][0] = acc[0][1] = acc[1][0] = acc[1][1] = 0ull;

        const float* wrow = &Wds[tx * 4];
        const float* prow = &Ps[ty * 2];
        ulonglong2 WAr = *(const ulonglong2*)wrow;
        float2     PAr = *(const float2*)prow;

#pragma unroll 2
        for (int r = 0; r < RNK; r += 2) {
            ulonglong2 WBr = *(const ulonglong2*)(wrow + 64);
            float2     PBr = *(const float2*)(prow + K2B);
            {
                unsigned long long p0 = pack2(PAr.x, PAr.x);
                unsigned long long p1 = pack2(PAr.y, PAr.y);
                ffma2(acc[0][0], p0, WAr.x); ffma2(acc[0][1], p0, WAr.y);
                ffma2(acc[1][0], p1, WAr.x); ffma2(acc[1][1], p1, WAr.y);
            }
            wrow += 128; prow += 2 * K2B;
            WAr = *(const ulonglong2*)wrow;
            PAr = *(const float2*)prow;
            {
                unsigned long long p0 = pack2(PBr.x, PBr.x);
                unsigned long long p1 = pack2(PBr.y, PBr.y);
                ffma2(acc[0][0], p0, WBr.x); ffma2(acc[0][1], p0, WBr.y);
                ffma2(acc[1][0], p1, WBr.x); ffma2(acc[1][1], p1, WBr.y);
            }
        }

        float4 bb = *(const float4*)&bdt[d0 + tx * 4];
#pragma unroll
        for (int i = 0; i < 2; i++) {
            float z0, z1, z2, z3;
            unpack2(acc[i][0], z0, z1);
            unpack2(acc[i][1], z2, z3);
            float4 dt4;
            dt4.x = softplus20(z0 + bb.x);
            dt4.y = softplus20(z1 + bb.y);
            dt4.z = softplus20(z2 + bb.z);
            dt4.w = softplus20(z3 + bb.w);
            *(float4*)&g_dt[(b0 + ty * 2 + i) * DIN + d0 + tx * 4] = dt4;
        }
    }

    if (blockIdx.x == 0) {
        for (int e = t; e < K2B * NST; e += 256) {
            int bi = e >> 4, n = e & 15;
            g_Ct[(b0 + bi) * NST + n] = g_Pt[(176 + n) * BATCH + b0 + bi];
        }
        if (t < K2B) {
            float s = 0.0f;
#pragma unroll
            for (int n = 0; n < NST; n++)
                s = fmaf(g_Pt[(160 + n) * BATCH + b0 + t],
                         g_Pt[(176 + n) * BATCH + b0 + t], s);
            g_SBC[b0 + t] = s;
        }
    }
}

// ---------- K3: stream h, produce y (warp-cooperative, full occupancy) ----------
#define NGRP (BATCH * DIN / 8)   // 163840
#define K3_GRID 1184

__global__ __launch_bounds__(256, 8)
void k3_stream(const float* __restrict__ h,
               const float* __restrict__ x,
               const float* __restrict__ Dv,
               float* __restrict__ out) {
    const int t     = threadIdx.x;
    const int lane  = t & 31;
    const int p     = lane >> 2;
    const int q     = lane & 3;
    const int wglob = blockIdx.x * 8 + (t >> 5);
    const int nw    = K3_GRID * 8;

    for (int g = wglob; g < NGRP; g += nw) {
        int b = g / 640;
        int c = g - b * 640;
        int d = c * 8 + p;

        float4 hv = __ldcs((const float4*)&h[((size_t)b * DIN + d) * NST + q * 4]);
        float4 a4 = *(const float4*)&g_As2[d * NST + q * 4];
        float4 c4 = *(const float4*)&g_Ct[b * NST + q * 4];
        float dtv = g_dt[b * DIN + d];

        float s = c4.x * (ex2f(dtv * a4.x) * hv.x);
        s = fmaf(c4.y, ex2f(dtv * a4.y) * hv.y, s);
        s = fmaf(c4.z, ex2f(dtv * a4.z) * hv.z, s);
        s = fmaf(c4.w, ex2f(dtv * a4.w) * hv.w, s);

        s += __shfl_xor_sync(0xffffffffu, s, 1);
        s += __shfl_xor_sync(0xffffffffu, s, 2);

        if (q == 0) {
            float xv = x[b * DIN + d];
            out[b * DIN + d] = s + xv * fmaf(dtv, g_SBC[b], Dv[d]);
        }
    }
}

// ---------- launch ----------
extern "C" void kernel_launch(void* const* d_in, const int* in_sizes, int n_in,
                              void* d_out, int out_size) {
    const float* x    = (const float*)d_in[0];
    const float* h    = (const float*)d_in[1];
    const float* Wd   = (const float*)d_in[2];
    const float* Wdt  = (const float*)d_in[3];
    const float* bdt  = (const float*)d_in[4];
    const float* Alog = (const float*)d_in[5];
    const float* WB   = (const float*)d_in[6];
    const float* WC   = (const float*)d_in[7];
    const float* Dv   = (const float*)d_in[8];
    float* out = (float*)d_out;

    cudaFuncSetAttribute(k2_dt, cudaFuncAttributeMaxDynamicSharedMemorySize, K2_SMEM);

    k1_proj<<<dim3(KSPLIT, BATCH / K1_BT), 256, K1_SMEM>>>(x, Wd, WB, WC, Alog);
    k1r_reduce<<<48, 256>>>();
    k2_dt<<<dim3(DIN / 128, BATCH / K2B), 256, K2_SMEM>>>(Wdt, bdt);
    k3_stream<<<K3_GRID, 256>>>(h, x, Dv, out);
}

// round 13
// speedup vs baseline: 1.7507x; 1.7507x over previous
#include <cuda_runtime.h>
#include <cstdint>

#define BATCH   256
#define DIN     5120
#define RNK     160
#define NST     16
#define NOUT    192   // 160 (dt_low) + 16 (Bp) + 16 (C)
#define KSPLIT  64

// Scratch
__device__ float g_Part[KSPLIT * BATCH * NOUT]; // split-K partials [ks][b][j]
__device__ float g_Pt[NOUT * BATCH];            // P^T [out][batch]
__device__ float g_dt[BATCH * DIN];             // softplus'd delta [b][d]
__device__ float g_As2[DIN * NST];              // -exp(A_log)*log2e
__device__ float g_Ct[BATCH * NST];             // C transposed [b][n]
__device__ float g_SBC[BATCH];                  // sum_n Bp*C per batch

// ---------- f32x2 helpers ----------
__device__ __forceinline__ unsigned long long pack2(float lo, float hi) {
    unsigned long long r;
    asm("mov.b64 %0, {%1, %2};" : "=l"(r)
        : "r"(__float_as_uint(lo)), "r"(__float_as_uint(hi)));
    return r;
}
__device__ __forceinline__ void unpack2(unsigned long long v, float& lo, float& hi) {
    unsigned int a, b;
    asm("mov.b64 {%0, %1}, %2;" : "=r"(a), "=r"(b) : "l"(v));
    lo = __uint_as_float(a);
    hi = __uint_as_float(b);
}
__device__ __forceinline__ void ffma2(unsigned long long& d,
                                      unsigned long long a,
                                      unsigned long long b) {
    asm("fma.rn.f32x2 %0, %1, %2, %0;" : "+l"(d) : "l"(a), "l"(b));
}
__device__ __forceinline__ float ex2f(float x) {
    float r;
    asm("ex2.approx.ftz.f32 %0, %1;" : "=f"(r) : "f"(x));
    return r;
}
__device__ __forceinline__ float softplus20(float z) {
    return (z > 20.0f) ? z : fmaxf(z, 0.0f) + log1pf(__expf(-fabsf(z)));
}

// ---------- K1: split-K proj GEMM, W direct from gmem ----------
// grid (64 ksplits of 80, 8 btiles of 32), block 256 = 8 warps.
// __launch_bounds__(256,2): reg cap 128 — the (256,3) version SPILLED (84-reg cap).
#define K1_KC 80
#define K1_BT 32
#define K1_SMEM (K1_KC * 33 * 4)     // Xst only, 10.5 KB

__global__ __launch_bounds__(256, 2)
void k1_proj(const float* __restrict__ x,
             const float* __restrict__ Wd,
             const float* __restrict__ WB,
             const float* __restrict__ WC,
             const float* __restrict__ Alog) {
    extern __shared__ float sm[];
    float* Xst = sm;                   // [k][b] 80 x 33

    const int t   = threadIdx.x;
    const int ks  = blockIdx.x;
    const int k0  = ks * K1_KC;
    const int b0  = blockIdx.y * K1_BT;
    const int cta = blockIdx.y * gridDim.x + blockIdx.x;   // 0..511

    // As2 precompute: first 256 CTAs x 320 elems (80 float4)
    if (cta < 256 && t < 80) {
        int idx = cta * 320 + t * 4;
        float4 a = *(const float4*)&Alog[idx];
        const float c = -1.44269504088896f;
        float4 r;
        r.x = c * __expf(a.x); r.y = c * __expf(a.y);
        r.z = c * __expf(a.z); r.w = c * __expf(a.w);
        *(float4*)&g_As2[idx] = r;
    }

    // load X transposed: 32 rows x 20 quads = 640 float4
    for (int e = t; e < K1_BT * (K1_KC / 4); e += 256) {
        int row = e / 20;
        int q   = e - row * 20;
        float4 v = *(const float4*)&x[(b0 + row) * DIN + k0 + q * 4];
        int base = (q * 4) * 33 + row;
        Xst[base]      = v.x;
        Xst[base + 33] = v.y;
        Xst[base + 66] = v.z;
        Xst[base + 99] = v.w;
    }
    __syncthreads();

    const int w    = t >> 5;
    const int lane = t & 31;
    const int jb   = w * 24;

    // per-quad uniform W pointers + strides
    const float* wptr[6];
    int wstr[6];
#pragma unroll
    for (int qd = 0; qd < 6; qd++) {
        int j = jb + qd * 4;
        if (j < RNK)      { wptr[qd] = Wd + (size_t)k0 * RNK + j;         wstr[qd] = RNK; }
        else if (j < 176) { wptr[qd] = WB + (size_t)k0 * NST + (j - 160); wstr[qd] = NST; }
        else              { wptr[qd] = WC + (size_t)k0 * NST + (j - 176); wstr[qd] = NST; }
    }

    unsigned long long acc[12];
#pragma unroll
    for (int j = 0; j < 12; j++) acc[j] = 0ull;

    // distance-1 double buffer of W rows in registers
    ulonglong2 WA[6];
#pragma unroll
    for (int qd = 0; qd < 6; qd++) {
        WA[qd] = *(const ulonglong2*)wptr[qd];
        wptr[qd] += wstr[qd];
    }
    const float* xp = &Xst[lane];
    float xA = xp[0];

#pragma unroll 1
    for (int k = 0; k < K1_KC - 1; k++) {
        ulonglong2 WN[6];
#pragma unroll
        for (int qd = 0; qd < 6; qd++) {
            WN[qd] = *(const ulonglong2*)wptr[qd];
            wptr[qd] += wstr[qd];
        }
        float xN = xp[(k + 1) * 33];

        unsigned long long x2 = pack2(xA, xA);
#pragma unroll
        for (int qd = 0; qd < 6; qd++) {
            ffma2(acc[2 * qd],     x2, WA[qd].x);
            ffma2(acc[2 * qd + 1], x2, WA[qd].y);
        }
#pragma unroll
        for (int qd = 0; qd < 6; qd++) WA[qd] = WN[qd];
        xA = xN;
    }
    {   // peeled last row
        unsigned long long x2 = pack2(xA, xA);
#pragma unroll
        for (int qd = 0; qd < 6; qd++) {
            ffma2(acc[2 * qd],     x2, WA[qd].x);
            ffma2(acc[2 * qd + 1], x2, WA[qd].y);
        }
    }

    // epilogue: plain stores of partials, [ks][b][j] layout
    {
        float v[24];
#pragma unroll
        for (int j = 0; j < 12; j++) unpack2(acc[j], v[2 * j], v[2 * j + 1]);
        size_t base = ((size_t)ks * BATCH + b0 + lane) * NOUT + jb;
#pragma unroll
        for (int p = 0; p < 6; p++)
            *(float4*)&g_Part[base + p * 4] = *(float4*)&v[p * 4];
    }
}

// ---------- K1R: reduce split-K partials -> g_Pt[j][b] ----------
__global__ __launch_bounds__(256)
void k1r_reduce() {
    int t  = blockIdx.x * 256 + threadIdx.x;   // 0..12287
    int b  = t / 48;
    int jq = t - b * 48;
    int j  = jq * 4;

    float4 s0 = {0,0,0,0}, s1 = {0,0,0,0}, s2 = {0,0,0,0}, s3 = {0,0,0,0};
    size_t base = (size_t)b * NOUT + j;
    const size_t stride = (size_t)BATCH * NOUT;
#pragma unroll 4
    for (int ks = 0; ks < KSPLIT; ks += 4) {
        float4 a0 = *(const float4*)&g_Part[base + (ks + 0) * stride];
        float4 a1 = *(const float4*)&g_Part[base + (ks + 1) * stride];
        float4 a2 = *(const float4*)&g_Part[base + (ks + 2) * stride];
        float4 a3 = *(const float4*)&g_Part[base + (ks + 3) * stride];
        s0.x += a0.x; s0.y += a0.y; s0.z += a0.z; s0.w += a0.w;
        s1.x += a1.x; s1.y += a1.y; s1.z += a1.z; s1.w += a1.w;
        s2.x += a2.x; s2.y += a2.y; s2.z += a2.z; s2.w += a2.w;
        s3.x += a3.x; s3.y += a3.y; s3.z += a3.z; s3.w += a3.w;
    }
    g_Pt[(j + 0) * BATCH + b] = (s0.x + s1.x) + (s2.x + s3.x);
    g_Pt[(j + 1) * BATCH + b] = (s0.y + s1.y) + (s2.y + s3.y);
    g_Pt[(j + 2) * BATCH + b] = (s0.z + s1.z) + (s2.z + s3.z);
    g_Pt[(j + 3) * BATCH + b] = (s0.w + s1.w) + (s2.w + s3.w);
}

// ---------- K2: dt = softplus(P_low @ W_dt + b_dt); also Ct + SBC ----------
// grid (40 d-blocks of 128, 8 btiles of 32), block 256, 3 CTAs/SM.
#define K2B 32
#define K2_SMEM (((RNK + 1) * 64 + (RNK + 1) * K2B) * 4)

__global__ __launch_bounds__(256, 3)
void k2_dt(const float* __restrict__ Wdt,
           const float* __restrict__ bdt) {
    extern __shared__ float sm[];
    float* Wds = sm;                      // [r][dj] (160+1) x 64
    float* Ps  = sm + (RNK + 1) * 64;     // [r][bi] (160+1) x 32

    const int t  = threadIdx.x;
    const int b0 = blockIdx.y * K2B;
    const int tx = t & 15;   // dj group of 4
    const int ty = t >> 4;   // bi group of 2

    for (int e = t; e < RNK * 8; e += 256) {
        int r = e >> 3, q = e & 7;
        *(float4*)&Ps[r * K2B + q * 4] = *(const float4*)&g_Pt[r * BATCH + b0 + q * 4];
    }

    for (int chunk = 0; chunk < 2; chunk++) {
        const int d0 = blockIdx.x * 128 + chunk * 64;
        __syncthreads();
        for (int e = t; e < RNK * 16; e += 256) {
            int r = e >> 4, q = e & 15;
            *(float4*)&Wds[r * 64 + q * 4] =
                *(const float4*)&Wdt[r * DIN + d0 + q * 4];
        }
        __syncthreads();

        unsigned long long acc[2][2];
        acc[0][0] = acc[0][1] = acc[1][0] = acc[1][1] = 0ull;

        const float* wrow = &Wds[tx * 4];
        const float* prow = &Ps[ty * 2];
        ulonglong2 WAr = *(const ulonglong2*)wrow;
        float2     PAr = *(const float2*)prow;

#pragma unroll 2
        for (int r = 0; r < RNK; r += 2) {
            ulonglong2 WBr = *(const ulonglong2*)(wrow + 64);
            float2     PBr = *(const float2*)(prow + K2B);
            {
                unsigned long long p0 = pack2(PAr.x, PAr.x);
                unsigned long long p1 = pack2(PAr.y, PAr.y);
                ffma2(acc[0][0], p0, WAr.x); ffma2(acc[0][1], p0, WAr.y);
                ffma2(acc[1][0], p1, WAr.x); ffma2(acc[1][1], p1, WAr.y);
            }
            wrow += 128; prow += 2 * K2B;
            WAr = *(const ulonglong2*)wrow;
            PAr = *(const float2*)prow;
            {
                unsigned long long p0 = pack2(PBr.x, PBr.x);
                unsigned long long p1 = pack2(PBr.y, PBr.y);
                ffma2(acc[0][0], p0, WBr.x); ffma2(acc[0][1], p0, WBr.y);
                ffma2(acc[1][0], p1, WBr.x); ffma2(acc[1][1], p1, WBr.y);
            }
        }

        float4 bb = *(const float4*)&bdt[d0 + tx * 4];
#pragma unroll
        for (int i = 0; i < 2; i++) {
            float z0, z1, z2, z3;
            unpack2(acc[i][0], z0, z1);
            unpack2(acc[i][1], z2, z3);
            float4 dt4;
            dt4.x = softplus20(z0 + bb.x);
            dt4.y = softplus20(z1 + bb.y);
            dt4.z = softplus20(z2 + bb.z);
            dt4.w = softplus20(z3 + bb.w);
            *(float4*)&g_dt[(b0 + ty * 2 + i) * DIN + d0 + tx * 4] = dt4;
        }
    }

    if (blockIdx.x == 0) {
        for (int e = t; e < K2B * NST; e += 256) {
            int bi = e >> 4, n = e & 15;
            g_Ct[(b0 + bi) * NST + n] = g_Pt[(176 + n) * BATCH + b0 + bi];
        }
        if (t < K2B) {
            float s = 0.0f;
#pragma unroll
            for (int n = 0; n < NST; n++)
                s = fmaf(g_Pt[(160 + n) * BATCH + b0 + t],
                         g_Pt[(176 + n) * BATCH + b0 + t], s);
            g_SBC[b0 + t] = s;
        }
    }
}

// ---------- K3: stream h, produce y (warp-cooperative, ILP-2, big grid) ----------
// group = (b, 8 consecutive d). 4 lanes per (b,d), lane q covers n = q*4..q*4+3.
#define NGRP (BATCH * DIN / 8)   // 163840
#define K3_GRID 1184

__global__ __launch_bounds__(256, 5)
void k3_stream(const float* __restrict__ h,
               const float* __restrict__ x,
               const float* __restrict__ Dv,
               float* __restrict__ out) {
    const int t     = threadIdx.x;
    const int lane  = t & 31;
    const int p     = lane >> 2;
    const int q     = lane & 3;
    const int wglob = blockIdx.x * 8 + (t >> 5);
    const int nw    = K3_GRID * 8;           // 9472

#pragma unroll 1
    for (int g = wglob; g < NGRP; g += 2 * nw) {
        const int g2 = g + nw;
        const bool has2 = (g2 < NGRP);

        int ba = g / 640,  ca = g - ba * 640,  da = ca * 8 + p;
        int idxa = ba * DIN + da;
        float4 hva = __ldcs((const float4*)&h[(size_t)idxa * NST + q * 4]);

        int bb = 0, db = 0, idxb = 0;
        float4 hvb = {0, 0, 0, 0};
        if (has2) {
            bb = g2 / 640; int cb = g2 - bb * 640; db = cb * 8 + p;
            idxb = bb * DIN + db;
            hvb = __ldcs((const float4*)&h[(size_t)idxb * NST + q * 4]);
        }

        float  dta = g_dt[idxa];
        float4 aa  = *(const float4*)&g_As2[da * NST + q * 4];
        float4 cca = *(const float4*)&g_Ct[ba * NST + q * 4];

        float sa = cca.x * (ex2f(dta * aa.x) * hva.x);
        sa = fmaf(cca.y, ex2f(dta * aa.y) * hva.y, sa);
        sa = fmaf(cca.z, ex2f(dta * aa.z) * hva.z, sa);
        sa = fmaf(cca.w, ex2f(dta * aa.w) * hva.w, sa);
        sa += __shfl_xor_sync(0xffffffffu, sa, 1);
        sa += __shfl_xor_sync(0xffffffffu, sa, 2);
        if (q == 0) {
            float xa = x[idxa];
            out[idxa] = sa + xa * fmaf(dta, g_SBC[ba], Dv[da]);
        }

        if (has2) {
            float  dtb = g_dt[idxb];
            float4 ab  = *(const float4*)&g_As2[db * NST + q * 4];
            float4 ccb = *(const float4*)&g_Ct[bb * NST + q * 4];

            float sb = ccb.x * (ex2f(dtb * ab.x) * hvb.x);
            sb = fmaf(ccb.y, ex2f(dtb * ab.y) * hvb.y, sb);
            sb = fmaf(ccb.z, ex2f(dtb * ab.z) * hvb.z, sb);
            sb = fmaf(ccb.w, ex2f(dtb * ab.w) * hvb.w, sb);
            sb += __shfl_xor_sync(0xffffffffu, sb, 1);
            sb += __shfl_xor_sync(0xffffffffu, sb, 2);
            if (q == 0) {
                float xb = x[idxb];
                out[idxb] = sb + xb * fmaf(dtb, g_SBC[bb], Dv[db]);
            }
        }
    }
}

// ---------- launch ----------
extern "C" void kernel_launch(void* const* d_in, const int* in_sizes, int n_in,
                              void* d_out, int out_size) {
    const float* x    = (const float*)d_in[0];
    const float* h    = (const float*)d_in[1];
    const float* Wd   = (const float*)d_in[2];
    const float* Wdt  = (const float*)d_in[3];
    const float* bdt  = (const float*)d_in[4];
    const float* Alog = (const float*)d_in[5];
    const float* WB   = (const float*)d_in[6];
    const float* WC   = (const float*)d_in[7];
    const float* Dv   = (const float*)d_in[8];
    float* out = (float*)d_out;

    cudaFuncSetAttribute(k2_dt, cudaFuncAttributeMaxDynamicSharedMemorySize, K2_SMEM);

    k1_proj<<<dim3(KSPLIT, BATCH / K1_BT), 256, K1_SMEM>>>(x, Wd, WB, WC, Alog);
    k1r_reduce<<<48, 256>>>();
    k2_dt<<<dim3(DIN / 128, BATCH / K2B), 256, K2_SMEM>>>(Wdt, bdt);
    k3_stream<<<K3_GRID, 256>>>(h, x, Dv, out);
}

// round 16
// speedup vs baseline: 2.2107x; 1.2627x over previous
#include <cuda_runtime.h>
#include <cstdint>

#define BATCH   256
#define DIN     5120
#define RNK     160
#define NST     16
#define NOUT    192   // 160 (dt_low) + 16 (Bp) + 16 (C)
#define KSPLIT  64

// Scratch
__device__ float g_Part[KSPLIT * BATCH * NOUT]; // split-K partials [ks][b][j]
__device__ float g_Pt[NOUT * BATCH];            // P^T [out][batch]
__device__ float g_dt[BATCH * DIN];             // softplus'd delta [b][d]
__device__ float g_As2[DIN * NST];              // -exp(A_log)*log2e
__device__ float g_Ct[BATCH * NST];             // C transposed [b][n]
__device__ float g_SBC[BATCH];                  // sum_n Bp*C per batch

// ---------- f32x2 helpers ----------
__device__ __forceinline__ unsigned long long pack2(float lo, float hi) {
    unsigned long long r;
    asm("mov.b64 %0, {%1, %2};" : "=l"(r)
        : "r"(__float_as_uint(lo)), "r"(__float_as_uint(hi)));
    return r;
}
__device__ __forceinline__ void unpack2(unsigned long long v, float& lo, float& hi) {
    unsigned int a, b;
    asm("mov.b64 {%0, %1}, %2;" : "=r"(a), "=r"(b) : "l"(v));
    lo = __uint_as_float(a);
    hi = __uint_as_float(b);
}
__device__ __forceinline__ void ffma2(unsigned long long& d,
                                      unsigned long long a,
                                      unsigned long long b) {
    asm("fma.rn.f32x2 %0, %1, %2, %0;" : "+l"(d) : "l"(a), "l"(b));
}
__device__ __forceinline__ float ex2f(float x) {
    float r;
    asm("ex2.approx.ftz.f32 %0, %1;" : "=f"(r) : "f"(x));
    return r;
}
__device__ __forceinline__ float softplus20(float z) {
    return (z > 20.0f) ? z : fmaxf(z, 0.0f) + log1pf(__expf(-fabsf(z)));
}

// ---------- K1: split-K proj GEMM, smem W, NO atomics, 3 CTAs/SM ----------
// grid (64 ksplits of 80, 8 btiles of 32), block 256 = 8 warps.
// Warp w handles 24 outputs [24w,24w+24) via 6 broadcast LDS.128 per k;
// lane handles batch b0+lane. Partials to g_Part[ks][b][j].
#define K1_KC 80
#define K1_BT 32
#define K1_WSOFF (K1_KC * 33)                       // 2640 floats (16B aligned)
#define K1_SMEM ((K1_KC * 33 + K1_KC * NOUT) * 4)   // 72000 B -> 3 CTAs/SM

__global__ __launch_bounds__(256, 3)
void k1_proj(const float* __restrict__ x,
             const float* __restrict__ Wd,
             const float* __restrict__ WB,
             const float* __restrict__ WC,
             const float* __restrict__ Alog) {
    extern __shared__ float sm[];
    float* Xst = sm;                   // [k][b] 80 x 33
    float* Ws  = sm + K1_WSOFF;        // [k][j] 80 x 192

    const int t   = threadIdx.x;
    const int ks  = blockIdx.x;
    const int k0  = ks * K1_KC;
    const int b0  = blockIdx.y * K1_BT;
    const int cta = blockIdx.y * gridDim.x + blockIdx.x;   // 0..511

    // As2 precompute: first 256 CTAs x 320 elems (80 float4)
    if (cta < 256 && t < 80) {
        int idx = cta * 320 + t * 4;
        float4 a = *(const float4*)&Alog[idx];
        const float c = -1.44269504088896f;
        float4 r;
        r.x = c * __expf(a.x); r.y = c * __expf(a.y);
        r.z = c * __expf(a.z); r.w = c * __expf(a.w);
        *(float4*)&g_As2[idx] = r;
    }

    // load X transposed: 32 rows x 20 quads = 640 float4
    for (int e = t; e < K1_BT * (K1_KC / 4); e += 256) {
        int row = e / 20;
        int q   = e - row * 20;
        float4 v = *(const float4*)&x[(b0 + row) * DIN + k0 + q * 4];
        int base = (q * 4) * 33 + row;
        Xst[base]      = v.x;
        Xst[base + 33] = v.y;
        Xst[base + 66] = v.z;
        Xst[base + 99] = v.w;
    }
    // load W concatenated: 80 rows x 48 quads = 3840 float4 (coalesced)
    for (int e = t; e < K1_KC * 48; e += 256) {
        int k  = e / 48;
        int j4 = (e - k * 48) * 4;
        int kk = k0 + k;
        float4 v;
        if (j4 < RNK)      v = *(const float4*)&Wd[kk * RNK + j4];
        else if (j4 < 176) v = *(const float4*)&WB[kk * NST + (j4 - 160)];
        else               v = *(const float4*)&WC[kk * NST + (j4 - 176)];
        *(float4*)&Ws[k * NOUT + j4] = v;
    }
    __syncthreads();

    const int w    = t >> 5;
    const int lane = t & 31;
    const int jb   = w * 24;

    unsigned long long acc[12];
#pragma unroll
    for (int j = 0; j < 12; j++) acc[j] = 0ull;

    const float* wp = &Ws[jb];      // 96B-aligned
    const float* xp = &Xst[lane];

#pragma unroll 2
    for (int k = 0; k < K1_KC; k++) {
        ulonglong2 w0 = ((const ulonglong2*)wp)[0];
        ulonglong2 w1 = ((const ulonglong2*)wp)[1];
        ulonglong2 w2 = ((const ulonglong2*)wp)[2];
        float xv = xp[0];
        unsigned long long x2 = pack2(xv, xv);
        ffma2(acc[0],  x2, w0.x); ffma2(acc[1],  x2, w0.y);
        ffma2(acc[2],  x2, w1.x); ffma2(acc[3],  x2, w1.y);
        ffma2(acc[4],  x2, w2.x); ffma2(acc[5],  x2, w2.y);
        ulonglong2 w3 = ((const ulonglong2*)wp)[3];
        ulonglong2 w4 = ((const ulonglong2*)wp)[4];
        ulonglong2 w5 = ((const ulonglong2*)wp)[5];
        ffma2(acc[6],  x2, w3.x); ffma2(acc[7],  x2, w3.y);
        ffma2(acc[8],  x2, w4.x); ffma2(acc[9],  x2, w4.y);
        ffma2(acc[10], x2, w5.x); ffma2(acc[11], x2, w5.y);
        wp += NOUT; xp += 33;
    }

    // epilogue: plain stores of partials, [ks][b][j] layout
    {
        float v[24];
#pragma unroll
        for (int j = 0; j < 12; j++) unpack2(acc[j], v[2 * j], v[2 * j + 1]);
        size_t base = ((size_t)ks * BATCH + b0 + lane) * NOUT + jb;
#pragma unroll
        for (int p = 0; p < 6; p++)
            *(float4*)&g_Part[base + p * 4] = *(float4*)&v[p * 4];
    }
}

// ---------- K1R: reduce split-K partials -> g_Pt[j][b] ----------
__global__ __launch_bounds__(256)
void k1r_reduce() {
    int t  = blockIdx.x * 256 + threadIdx.x;   // 0..12287
    int b  = t / 48;
    int jq = t - b * 48;
    int j  = jq * 4;

    float4 s0 = {0,0,0,0}, s1 = {0,0,0,0}, s2 = {0,0,0,0}, s3 = {0,0,0,0};
    size_t base = (size_t)b * NOUT + j;
    const size_t stride = (size_t)BATCH * NOUT;
#pragma unroll 4
    for (int ks = 0; ks < KSPLIT; ks += 4) {
        float4 a0 = *(const float4*)&g_Part[base + (ks + 0) * stride];
        float4 a1 = *(const float4*)&g_Part[base + (ks + 1) * stride];
        float4 a2 = *(const float4*)&g_Part[base + (ks + 2) * stride];
        float4 a3 = *(const float4*)&g_Part[base + (ks + 3) * stride];
        s0.x += a0.x; s0.y += a0.y; s0.z += a0.z; s0.w += a0.w;
        s1.x += a1.x; s1.y += a1.y; s1.z += a1.z; s1.w += a1.w;
        s2.x += a2.x; s2.y += a2.y; s2.z += a2.z; s2.w += a2.w;
        s3.x += a3.x; s3.y += a3.y; s3.z += a3.z; s3.w += a3.w;
    }
    g_Pt[(j + 0) * BATCH + b] = (s0.x + s1.x) + (s2.x + s3.x);
    g_Pt[(j + 1) * BATCH + b] = (s0.y + s1.y) + (s2.y + s3.y);
    g_Pt[(j + 2) * BATCH + b] = (s0.z + s1.z) + (s2.z + s3.z);
    g_Pt[(j + 3) * BATCH + b] = (s0.w + s1.w) + (s2.w + s3.w);
}

// ---------- K2: dt = softplus(P_low @ W_dt + b_dt); also Ct + SBC ----------
// grid (40 d-blocks of 128, 8 btiles of 32), block 256, 3 CTAs/SM.
#define K2B 32
#define K2_SMEM (((RNK + 1) * 64 + (RNK + 1) * K2B) * 4)

__global__ __launch_bounds__(256, 3)
void k2_dt(const float* __restrict__ Wdt,
           const float* __restrict__ bdt) {
    extern __shared__ float sm[];
    float* Wds = sm;                      // [r][dj] (160+1) x 64
    float* Ps  = sm + (RNK + 1) * 64;     // [r][bi] (160+1) x 32

    const int t  = threadIdx.x;
    const int b0 = blockIdx.y * K2B;
    const int tx = t & 15;   // dj group of 4
    const int ty = t >> 4;   // bi group of 2

    for (int e = t; e < RNK * 8; e += 256) {
        int r = e >> 3, q = e & 7;
        *(float4*)&Ps[r * K2B + q * 4] = *(const float4*)&g_Pt[r * BATCH + b0 + q * 4];
    }

    for (int chunk = 0; chunk < 2; chunk++) {
        const int d0 = blockIdx.x * 128 + chunk * 64;
        __syncthreads();
        for (int e = t; e < RNK * 16; e += 256) {
            int r = e >> 4, q = e & 15;
            *(float4*)&Wds[r * 64 + q * 4] =
                *(const float4*)&Wdt[r * DIN + d0 + q * 4];
        }
        __syncthreads();

        unsigned long long acc[2][2];
        acc[0][0] = acc[0][1] = acc[1][0] = acc[1][1] = 0ull;

        const float* wrow = &Wds[tx * 4];
        const float* prow = &Ps[ty * 2];
        ulonglong2 WAr = *(const ulonglong2*)wrow;
        float2     PAr = *(const float2*)prow;

#pragma unroll 2
        for (int r = 0; r < RNK; r += 2) {
            ulonglong2 WBr = *(const ulonglong2*)(wrow + 64);
            float2     PBr = *(const float2*)(prow + K2B);
            {
                unsigned long long p0 = pack2(PAr.x, PAr.x);
                unsigned long long p1 = pack2(PAr.y, PAr.y);
                ffma2(acc[0][0], p0, WAr.x); ffma2(acc[0][1], p0, WAr.y);
                ffma2(acc[1][0], p1, WAr.x); ffma2(acc[1][1], p1, WAr.y);
            }
            wrow += 128; prow += 2 * K2B;
            WAr = *(const ulonglong2*)wrow;
            PAr = *(const float2*)prow;
            {
                unsigned long long p0 = pack2(PBr.x, PBr.x);
                unsigned long long p1 = pack2(PBr.y, PBr.y);
                ffma2(acc[0][0], p0, WBr.x); ffma2(acc[0][1], p0, WBr.y);
                ffma2(acc[1][0], p1, WBr.x); ffma2(acc[1][1], p1, WBr.y);
            }
        }

        float4 bb = *(const float4*)&bdt[d0 + tx * 4];
#pragma unroll
        for (int i = 0; i < 2; i++) {
            float z0, z1, z2, z3;
            unpack2(acc[i][0], z0, z1);
            unpack2(acc[i][1], z2, z3);
            float4 dt4;
            dt4.x = softplus20(z0 + bb.x);
            dt4.y = softplus20(z1 + bb.y);
            dt4.z = softplus20(z2 + bb.z);
            dt4.w = softplus20(z3 + bb.w);
            *(float4*)&g_dt[(b0 + ty * 2 + i) * DIN + d0 + tx * 4] = dt4;
        }
    }

    if (blockIdx.x == 0) {
        for (int e = t; e < K2B * NST; e += 256) {
            int bi = e >> 4, n = e & 15;
            g_Ct[(b0 + bi) * NST + n] = g_Pt[(176 + n) * BATCH + b0 + bi];
        }
        if (t < K2B) {
            float s = 0.0f;
#pragma unroll
            for (int n = 0; n < NST; n++)
                s = fmaf(g_Pt[(160 + n) * BATCH + b0 + t],
                         g_Pt[(176 + n) * BATCH + b0 + t], s);
            g_SBC[b0 + t] = s;
        }
    }
}

// ---------- K3: stream h, produce y (R10 config: simple body, full occ) ----------
#define NGRP (BATCH * DIN / 8)   // 163840
#define K3_GRID 1184

__global__ __launch_bounds__(256, 8)
void k3_stream(const float* __restrict__ h,
               const float* __restrict__ x,
               const float* __restrict__ Dv,
               float* __restrict__ out) {
    const int t     = threadIdx.x;
    const int lane  = t & 31;
    const int p     = lane >> 2;
    const int q     = lane & 3;
    const int wglob = blockIdx.x * 8 + (t >> 5);
    const int nw    = K3_GRID * 8;

    for (int g = wglob; g < NGRP; g += nw) {
        int b = g / 640;
        int c = g - b * 640;
        int d = c * 8 + p;

        float4 hv = __ldcs((const float4*)&h[((size_t)b * DIN + d) * NST + q * 4]);
        float4 a4 = *(const float4*)&g_As2[d * NST + q * 4];
        float4 c4 = *(const float4*)&g_Ct[b * NST + q * 4];
        float dtv = g_dt[b * DIN + d];

        float s = c4.x * (ex2f(dtv * a4.x) * hv.x);
        s = fmaf(c4.y, ex2f(dtv * a4.y) * hv.y, s);
        s = fmaf(c4.z, ex2f(dtv * a4.z) * hv.z, s);
        s = fmaf(c4.w, ex2f(dtv * a4.w) * hv.w, s);

        s += __shfl_xor_sync(0xffffffffu, s, 1);
        s += __shfl_xor_sync(0xffffffffu, s, 2);

        if (q == 0) {
            float xv = x[b * DIN + d];
            out[b * DIN + d] = s + xv * fmaf(dtv, g_SBC[b], Dv[d]);
        }
    }
}

// ---------- launch ----------
extern "C" void kernel_launch(void* const* d_in, const int* in_sizes, int n_in,
                              void* d_out, int out_size) {
    const float* x    = (const float*)d_in[0];
    const float* h    = (const float*)d_in[1];
    const float* Wd   = (const float*)d_in[2];
    const float* Wdt  = (const float*)d_in[3];
    const float* bdt  = (const float*)d_in[4];
    const float* Alog = (const float*)d_in[5];
    const float* WB   = (const float*)d_in[6];
    const float* WC   = (const float*)d_in[7];
    const float* Dv   = (const float*)d_in[8];
    float* out = (float*)d_out;

    cudaFuncSetAttribute(k1_proj, cudaFuncAttributeMaxDynamicSharedMemorySize, K1_SMEM);
    cudaFuncSetAttribute(k2_dt,   cudaFuncAttributeMaxDynamicSharedMemorySize, K2_SMEM);

    k1_proj<<<dim3(KSPLIT, BATCH / K1_BT), 256, K1_SMEM>>>(x, Wd, WB, WC, Alog);
    k1r_reduce<<<48, 256>>>();
    k2_dt<<<dim3(DIN / 128, BATCH / K2B), 256, K2_SMEM>>>(Wdt, bdt);
    k3_stream<<<K3_GRID, 256>>>(h, x, Dv, out);
}